// round 10
// baseline (speedup 1.0000x reference)
#include <cuda_runtime.h>
#include <cuda_fp16.h>
#include <mma.h>

using namespace nvcuda;

#define IN_F     4096
#define OUT_F    4096
#define RANK     64
#define RANK_EXT 80   // 64 + 16 ext cols (col 64 = bias term, 65..79 = 0)
#define M_ROWS   8192

__device__ __half g_win [RANK * IN_F];        // [64][4096] f16
__device__ __half g_wout[OUT_F * RANK_EXT];   // [4096][80] f16 (col64=bias)

// ---------------------------------------------------------------------------
// helpers
// ---------------------------------------------------------------------------
__device__ __forceinline__ void cp_async16(void* smem_dst, const void* gsrc) {
    unsigned s = (unsigned)__cvta_generic_to_shared(smem_dst);
    asm volatile("cp.async.cg.shared.global [%0], [%1], 16;\n" :: "r"(s), "l"(gsrc));
}
__device__ __forceinline__ void cp_async_commit() {
    asm volatile("cp.async.commit_group;\n");
}
template <int N>
__device__ __forceinline__ void cp_async_wait() {
    asm volatile("cp.async.wait_group %0;\n" :: "n"(N));
}

__device__ __forceinline__ void soft_threshold4(float4 w, float s,
                                                float& o0, float& o1, float& o2, float& o3) {
    float m0 = fabsf(w.x), m1 = fabsf(w.y), m2 = fabsf(w.z), m3 = fabsf(w.w);
    float lo01 = fminf(m0, m1), hi01 = fmaxf(m0, m1);
    float lo23 = fminf(m2, m3), hi23 = fmaxf(m2, m3);
    float t = fminf(fmaxf(lo01, lo23), fminf(hi01, hi23));  // 2nd-smallest
    o0 = copysignf(fmaxf(m0 - t, 0.0f), w.x) * s;
    o1 = copysignf(fmaxf(m1 - t, 0.0f), w.y) * s;
    o2 = copysignf(fmaxf(m2 - t, 0.0f), w.z) * s;
    o3 = copysignf(fmaxf(m3 - t, 0.0f), w.w) * s;
}

// ---------------------------------------------------------------------------
// Weight prep: threshold+scale -> g_win, g_wout(+bias ext col)
// ---------------------------------------------------------------------------
__global__ void prep_weights_kernel(const float* __restrict__ win,
                                    const float* __restrict__ wout,
                                    const float* __restrict__ bias,
                                    const float* __restrict__ scale_in,
                                    const float* __restrict__ scale_out) {
    const int NGI = RANK * IN_F / 4;    // 65536
    const int NGO = OUT_F * RANK / 4;   // 65536
    int idx = blockIdx.x * blockDim.x + threadIdx.x;
    if (idx < NGI) {
        float4 w = reinterpret_cast<const float4*>(win)[idx];
        float o0, o1, o2, o3;
        soft_threshold4(w, __ldg(scale_in), o0, o1, o2, o3);
        __half2* dst = reinterpret_cast<__half2*>(g_win) + idx * 2;
        dst[0] = __floats2half2_rn(o0, o1);
        dst[1] = __floats2half2_rn(o2, o3);
    } else if (idx < NGI + NGO) {
        int j = idx - NGI;
        int o = j >> 4;
        int c = j & 15;
        float4 w = reinterpret_cast<const float4*>(wout)[j];
        float o0, o1, o2, o3;
        soft_threshold4(w, __ldg(scale_out), o0, o1, o2, o3);
        __half2* dst = reinterpret_cast<__half2*>(g_wout + o * RANK_EXT + c * 4);
        dst[0] = __floats2half2_rn(o0, o1);
        dst[1] = __floats2half2_rn(o2, o3);
    } else if (idx < NGI + NGO + OUT_F) {
        int r = idx - NGI - NGO;
        __half2* d = reinterpret_cast<__half2*>(g_wout + r * RANK_EXT + RANK);
        d[0] = __halves2half2(__float2half(bias[r]), __float2half(0.0f));
        #pragma unroll
        for (int i = 1; i < 8; i++) d[i] = __half2half2(__float2half(0.0f));
    }
}

// ---------------------------------------------------------------------------
// Fused kernel: per CTA (64 m-rows):
//   Phase 1: xp[64,64] = f16(x[m0:m0+64,:]) @ g_win^T  (K=4096, BK=128,
//            double-buffered smem + 2-deep register prefetch)
//   Stage:   acc -> Cs(f32, alias A0) -> Ps(f16 [64][88], alias A1, +ext cols)
//   Phase 2: loop 32 N-tiles: out[m0:+64, n0:+128] = (Ps . Ws_ext)/64
//            (Ws double-buffered cp.async, preloaded at kernel start;
//             direct store_matrix_sync epilogue)
// ---------------------------------------------------------------------------
#define F_LDA 136   // phase-1 smem stride (halves)
#define F_LDC 68    // f32 staging stride
#define F_LDP 88    // Ps / Ws stride (halves)
// smem layout (halves): A0=0, A1=8704, B0=17408, B1=26112, WS0=34816, WS1=46080
#define F_SM_HALVES (34816 + 2 * 128 * F_LDP)   // 57344 halves = 114688 B

__global__ __launch_bounds__(256, 1)
void fused_kernel(const float* __restrict__ x, float* __restrict__ out) {
    extern __shared__ __half sm[];
    __half* A0 = sm;
    __half* A1 = sm + 8704;
    __half* B0 = sm + 17408;
    __half* B1 = sm + 26112;
    __half* WsBuf[2] = { sm + 34816, sm + 34816 + 128 * F_LDP };
    float*  Cs = reinterpret_cast<float*>(A0);   // [64][68]
    __half* Ps = A1;                             // [64][88]

    const int tid  = threadIdx.x;
    const int warp = tid >> 5;
    const int m0   = blockIdx.x * 64;

    // ---- issue Ws preloads for n-tiles 0 and 1 (arrive during phase 1) ----
    auto load_ws = [&](__half* W, int n0) {
        #pragma unroll
        for (int it = 0; it < 5; it++) {
            int c = tid + it * 256;
            int row = c / 10, off = c % 10;
            cp_async16(W + row * F_LDP + off * 8,
                       g_wout + (size_t)(n0 + row) * RANK_EXT + off * 8);
        }
    };
    load_ws(WsBuf[0], 0);
    cp_async_commit();
    load_ws(WsBuf[1], 128);
    cp_async_commit();

    // ======================= Phase 1: GEMM1 =======================
    {
        const int wm = warp & 3;   // 16 rows
        const int wn = warp >> 2;  // 32 cols

        wmma::fragment<wmma::accumulator, 16, 16, 16, float> acc[2];
        wmma::fill_fragment(acc[0], 0.0f);
        wmma::fill_fragment(acc[1], 0.0f);

        const int NK = IN_F / 128;  // 32

        float4 xa0[8], xa1[8];
        int4   wb0[4], wb1[4];

        auto ldx = [&](float4* xa, int kt) {
            #pragma unroll
            for (int it = 0; it < 8; it++) {
                int i = tid + it * 256;
                int row = i >> 5, c4 = i & 31;   // 32 float4 per 128-f32 row
                xa[it] = __ldcs(reinterpret_cast<const float4*>(
                    &x[(size_t)(m0 + row) * IN_F + kt * 128 + c4 * 4]));
            }
        };
        auto ldw = [&](int4* wb, int kt) {
            #pragma unroll
            for (int it = 0; it < 4; it++) {
                int i = tid + it * 256;
                int row = i >> 4, c8 = i & 15;   // 16 int4 per 128-half row
                wb[it] = *reinterpret_cast<const int4*>(
                    &g_win[row * IN_F + kt * 128 + c8 * 8]);
            }
        };
        auto stage = [&](__half* A, __half* B, const float4* xa, const int4* wb) {
            #pragma unroll
            for (int it = 0; it < 8; it++) {
                int i = tid + it * 256;
                int row = i >> 5, c4 = i & 31;
                __half* p = &A[row * F_LDA + c4 * 4];
                reinterpret_cast<__half2*>(p)[0] = __floats2half2_rn(xa[it].x, xa[it].y);
                reinterpret_cast<__half2*>(p)[1] = __floats2half2_rn(xa[it].z, xa[it].w);
            }
            #pragma unroll
            for (int it = 0; it < 4; it++) {
                int i = tid + it * 256;
                int row = i >> 4, c8 = i & 15;
                *reinterpret_cast<int4*>(&B[row * F_LDA + c8 * 8]) = wb[it];
            }
        };
        auto mma = [&](const __half* A, const __half* B) {
            #pragma unroll
            for (int k4 = 0; k4 < 8; k4++) {
                wmma::fragment<wmma::matrix_a, 16, 16, 16, __half, wmma::row_major> a;
                wmma::load_matrix_sync(a, &A[(wm * 16) * F_LDA + k4 * 16], F_LDA);
                #pragma unroll
                for (int j = 0; j < 2; j++) {
                    wmma::fragment<wmma::matrix_b, 16, 16, 16, __half, wmma::col_major> b;
                    wmma::load_matrix_sync(b, &B[(wn * 32 + j * 16) * F_LDA + k4 * 16], F_LDA);
                    wmma::mma_sync(acc[j], a, b, acc[j]);
                }
            }
        };

        ldx(xa0, 0); ldw(wb0, 0);
        ldx(xa1, 1); ldw(wb1, 1);

        for (int kt = 0; kt < NK; kt += 2) {
            stage(A0, B0, xa0, wb0);
            __syncthreads();
            if (kt + 2 < NK) { ldx(xa0, kt + 2); ldw(wb0, kt + 2); }
            mma(A0, B0);

            stage(A1, B1, xa1, wb1);
            __syncthreads();
            if (kt + 3 < NK) { ldx(xa1, kt + 3); ldw(wb1, kt + 3); }
            mma(A1, B1);
        }
        // last barrier was before mma(A1,B1); mma(A0,B0) reads of A0 are all
        // complete for every warp -> safe to write Cs (=A0) now.
        #pragma unroll
        for (int j = 0; j < 2; j++)
            wmma::store_matrix_sync(&Cs[(wm * 16) * F_LDC + wn * 32 + j * 16],
                                    acc[j], F_LDC, wmma::mem_row_major);
        __syncthreads();   // Cs complete; all mma(A1,..) reads done -> Ps (=A1) writable

        // convert Cs -> Ps (f16, stride 88) + ext cols (col64=1, 65..79=0)
        #pragma unroll
        for (int it = 0; it < 11; it++) {   // 64*44 half2 = 2816 / 256
            int c = tid + it * 256;
            if (c < 64 * 44) {
                int row = c / 44, c2 = c % 44;
                __half2 h;
                if (c2 < 32) {
                    h = __floats2half2_rn(Cs[row * F_LDC + c2 * 2],
                                          Cs[row * F_LDC + c2 * 2 + 1]);
                } else if (c2 == 32) {
                    h = __halves2half2(__float2half(1.0f), __float2half(0.0f));
                } else {
                    h = __half2half2(__float2half(0.0f));
                }
                reinterpret_cast<__half2*>(Ps)[row * 44 + c2] = h;
            }
        }
        __syncthreads();
    }

    // ======================= Phase 2: GEMM2 =======================
    {
        const int wm = warp & 1;   // 32 rows
        const int wn = warp >> 1;  // 32 cols
        const float scaling = 1.0f / (float)RANK;
        const int NT = OUT_F / 128;  // 32

        for (int t = 0; t < NT; t++) {
            const int n0 = t * 128;
            __half* Ws = WsBuf[t & 1];

            cp_async_wait<1>();     // tile t resident
            __syncthreads();

            wmma::fragment<wmma::accumulator, 16, 16, 16, float> acc[2][2];
            #pragma unroll
            for (int i = 0; i < 2; i++)
                #pragma unroll
                for (int j = 0; j < 2; j++) wmma::fill_fragment(acc[i][j], 0.0f);

            #pragma unroll
            for (int k4 = 0; k4 < 5; k4++) {   // K = 80
                wmma::fragment<wmma::matrix_a, 16, 16, 16, __half, wmma::row_major> a[2];
                #pragma unroll
                for (int i = 0; i < 2; i++)
                    wmma::load_matrix_sync(a[i], &Ps[(wm * 32 + i * 16) * F_LDP + k4 * 16], F_LDP);
                #pragma unroll
                for (int j = 0; j < 2; j++) {
                    wmma::fragment<wmma::matrix_b, 16, 16, 16, __half, wmma::col_major> b;
                    wmma::load_matrix_sync(b, &Ws[(wn * 32 + j * 16) * F_LDP + k4 * 16], F_LDP);
                    #pragma unroll
                    for (int i = 0; i < 2; i++)
                        wmma::mma_sync(acc[i][j], a[i], b, acc[i][j]);
                }
            }

            #pragma unroll
            for (int i = 0; i < 2; i++)
                #pragma unroll
                for (int j = 0; j < 2; j++) {
                    #pragma unroll
                    for (int e = 0; e < acc[i][j].num_elements; e++)
                        acc[i][j].x[e] *= scaling;
                    wmma::store_matrix_sync(
                        &out[(size_t)(m0 + wm * 32 + i * 16) * OUT_F + n0 + wn * 32 + j * 16],
                        acc[i][j], OUT_F, wmma::mem_row_major);
                }

            __syncthreads();        // all warps done reading Ws[t&1]
            if (t + 2 < NT) {       // prefetch tile t+2 into the buffer just freed
                load_ws(WsBuf[t & 1], n0 + 256);
            }
            cp_async_commit();      // keep group count in lockstep with waits
        }
    }
}

// ---------------------------------------------------------------------------
// Launcher
// ---------------------------------------------------------------------------
extern "C" void kernel_launch(void* const* d_in, const int* in_sizes, int n_in,
                              void* d_out, int out_size) {
    const float* x         = (const float*)d_in[0];
    const float* weight_in = (const float*)d_in[1];
    const float* weight_out= (const float*)d_in[2];
    const float* bias      = (const float*)d_in[3];
    const float* scale_in  = (const float*)d_in[4];
    const float* scale_out = (const float*)d_in[5];
    float* out = (float*)d_out;

    const int M = in_sizes[0] / IN_F;  // 8192

    {
        int total = RANK * IN_F / 4 + OUT_F * RANK / 4 + OUT_F;
        prep_weights_kernel<<<(total + 255) / 256, 256>>>(
            weight_in, weight_out, bias, scale_in, scale_out);
    }
    {
        size_t smem = (size_t)F_SM_HALVES * sizeof(__half);  // 114688 B
        cudaFuncSetAttribute(fused_kernel,
                             cudaFuncAttributeMaxDynamicSharedMemorySize, (int)smem);
        fused_kernel<<<M / 64, 256, smem>>>(x, out);
    }
}

// round 11
// speedup vs baseline: 1.0523x; 1.0523x over previous
#include <cuda_runtime.h>
#include <cuda_fp16.h>
#include <mma.h>

using namespace nvcuda;

#define IN_F     4096
#define OUT_F    4096
#define RANK     64
#define RANK_EXT 80   // 64 + 16 ext cols (col 64 = bias term, 65..79 = 0)
#define M_ROWS   8192

__device__ __half g_win [RANK * IN_F];          // [64][4096] f16
__device__ __half g_wout[OUT_F * RANK_EXT];     // [4096][80] f16 (col64=bias)
__device__ __half g_xp  [M_ROWS * RANK_EXT];    // [8192][80] f16 (col64=1.0)
__device__ float  g_xp32[2 * M_ROWS * RANK];    // K-split partials, f32

// ---------------------------------------------------------------------------
// helpers
// ---------------------------------------------------------------------------
__device__ __forceinline__ void cp_async16(void* smem_dst, const void* gsrc) {
    unsigned s = (unsigned)__cvta_generic_to_shared(smem_dst);
    asm volatile("cp.async.cg.shared.global [%0], [%1], 16;\n" :: "r"(s), "l"(gsrc));
}
__device__ __forceinline__ void cp_async_commit() {
    asm volatile("cp.async.commit_group;\n");
}
template <int N>
__device__ __forceinline__ void cp_async_wait() {
    asm volatile("cp.async.wait_group %0;\n" :: "n"(N));
}

__device__ __forceinline__ void soft_threshold4(float4 w, float s,
                                                float& o0, float& o1, float& o2, float& o3) {
    float m0 = fabsf(w.x), m1 = fabsf(w.y), m2 = fabsf(w.z), m3 = fabsf(w.w);
    float lo01 = fminf(m0, m1), hi01 = fmaxf(m0, m1);
    float lo23 = fminf(m2, m3), hi23 = fmaxf(m2, m3);
    float t = fminf(fmaxf(lo01, lo23), fminf(hi01, hi23));  // 2nd-smallest
    o0 = copysignf(fmaxf(m0 - t, 0.0f), w.x) * s;
    o1 = copysignf(fmaxf(m1 - t, 0.0f), w.y) * s;
    o2 = copysignf(fmaxf(m2 - t, 0.0f), w.z) * s;
    o3 = copysignf(fmaxf(m3 - t, 0.0f), w.w) * s;
}

// ---------------------------------------------------------------------------
// Weight prep: threshold+scale -> g_win, g_wout(+bias ext col)
// ---------------------------------------------------------------------------
__global__ void prep_weights_kernel(const float* __restrict__ win,
                                    const float* __restrict__ wout,
                                    const float* __restrict__ bias,
                                    const float* __restrict__ scale_in,
                                    const float* __restrict__ scale_out) {
    const int NGI = RANK * IN_F / 4;    // 65536
    const int NGO = OUT_F * RANK / 4;   // 65536
    int idx = blockIdx.x * blockDim.x + threadIdx.x;
    if (idx < NGI) {
        float4 w = reinterpret_cast<const float4*>(win)[idx];
        float o0, o1, o2, o3;
        soft_threshold4(w, __ldg(scale_in), o0, o1, o2, o3);
        __half2* dst = reinterpret_cast<__half2*>(g_win) + idx * 2;
        dst[0] = __floats2half2_rn(o0, o1);
        dst[1] = __floats2half2_rn(o2, o3);
    } else if (idx < NGI + NGO) {
        int j = idx - NGI;
        int o = j >> 4;
        int c = j & 15;
        float4 w = reinterpret_cast<const float4*>(wout)[j];
        float o0, o1, o2, o3;
        soft_threshold4(w, __ldg(scale_out), o0, o1, o2, o3);
        __half2* dst = reinterpret_cast<__half2*>(g_wout + o * RANK_EXT + c * 4);
        dst[0] = __floats2half2_rn(o0, o1);
        dst[1] = __floats2half2_rn(o2, o3);
    } else if (idx < NGI + NGO + OUT_F) {
        int r = idx - NGI - NGO;
        __half2* d = reinterpret_cast<__half2*>(g_wout + r * RANK_EXT + RANK);
        d[0] = __halves2half2(__float2half(bias[r]), __float2half(0.0f));
        #pragma unroll
        for (int i = 1; i < 8; i++) d[i] = __half2half2(__float2half(0.0f));
    }
}

// ---------------------------------------------------------------------------
// GEMM1 (K-split x2): xp32[ks][m,r] = sum_{k in half ks} f16(x[m,k])*g_win[r,k]
// BM=64, BK=64, grid (128, 2), 2 CTAs/SM, double-buffered, 2-deep prefetch.
// ---------------------------------------------------------------------------
#define G1_LDA 72   // half, padded

__global__ __launch_bounds__(256, 2)
void gemm1_kernel(const float* __restrict__ x) {
    extern __shared__ __half sm1[];
    __half* A0 = sm1;                   // [64][72]
    __half* A1 = sm1 + 64 * G1_LDA;
    __half* B0 = sm1 + 2 * 64 * G1_LDA;
    __half* B1 = sm1 + 3 * 64 * G1_LDA;

    const int tid  = threadIdx.x;
    const int warp = tid >> 5;
    const int wm   = warp & 3;   // 16 rows
    const int wn   = warp >> 2;  // 32 cols
    const int m0   = blockIdx.x * 64;
    const int ks   = blockIdx.y;
    const int k0   = ks * (IN_F / 2);

    wmma::fragment<wmma::accumulator, 16, 16, 16, float> acc[2];
    wmma::fill_fragment(acc[0], 0.0f);
    wmma::fill_fragment(acc[1], 0.0f);

    const int NK = (IN_F / 2) / 64;  // 32

    float4 xa0[4], xa1[4];
    int4   wb0[2], wb1[2];

    auto ldx = [&](float4* xa, int kt) {
        #pragma unroll
        for (int it = 0; it < 4; it++) {
            int i = tid + it * 256;
            int row = i >> 4, c4 = i & 15;
            xa[it] = __ldcs(reinterpret_cast<const float4*>(
                &x[(size_t)(m0 + row) * IN_F + k0 + kt * 64 + c4 * 4]));
        }
    };
    auto ldw = [&](int4* wb, int kt) {
        #pragma unroll
        for (int it = 0; it < 2; it++) {
            int i = tid + it * 256;
            int row = i >> 3, c8 = i & 7;
            wb[it] = *reinterpret_cast<const int4*>(
                &g_win[row * IN_F + k0 + kt * 64 + c8 * 8]);
        }
    };
    auto stage = [&](__half* A, __half* B, const float4* xa, const int4* wb) {
        #pragma unroll
        for (int it = 0; it < 4; it++) {
            int i = tid + it * 256;
            int row = i >> 4, c4 = i & 15;
            __half* p = &A[row * G1_LDA + c4 * 4];
            reinterpret_cast<__half2*>(p)[0] = __floats2half2_rn(xa[it].x, xa[it].y);
            reinterpret_cast<__half2*>(p)[1] = __floats2half2_rn(xa[it].z, xa[it].w);
        }
        #pragma unroll
        for (int it = 0; it < 2; it++) {
            int i = tid + it * 256;
            int row = i >> 3, c8 = i & 7;
            *reinterpret_cast<int4*>(&B[row * G1_LDA + c8 * 8]) = wb[it];
        }
    };
    auto mma = [&](const __half* A, const __half* B) {
        #pragma unroll
        for (int k4 = 0; k4 < 4; k4++) {
            wmma::fragment<wmma::matrix_a, 16, 16, 16, __half, wmma::row_major> a;
            wmma::load_matrix_sync(a, &A[(wm * 16) * G1_LDA + k4 * 16], G1_LDA);
            #pragma unroll
            for (int j = 0; j < 2; j++) {
                wmma::fragment<wmma::matrix_b, 16, 16, 16, __half, wmma::col_major> b;
                wmma::load_matrix_sync(b, &B[(wn * 32 + j * 16) * G1_LDA + k4 * 16], G1_LDA);
                wmma::mma_sync(acc[j], a, b, acc[j]);
            }
        }
    };

    ldx(xa0, 0); ldw(wb0, 0);
    ldx(xa1, 1); ldw(wb1, 1);

    for (int kt = 0; kt < NK; kt += 2) {
        stage(A0, B0, xa0, wb0);
        __syncthreads();
        if (kt + 2 < NK) { ldx(xa0, kt + 2); ldw(wb0, kt + 2); }
        mma(A0, B0);

        stage(A1, B1, xa1, wb1);
        __syncthreads();
        if (kt + 3 < NK) { ldx(xa1, kt + 3); ldw(wb1, kt + 3); }
        mma(A1, B1);
    }

    float* outp = g_xp32 + (size_t)ks * M_ROWS * RANK;
    #pragma unroll
    for (int j = 0; j < 2; j++)
        wmma::store_matrix_sync(&outp[(size_t)(m0 + wm * 16) * RANK + wn * 32 + j * 16],
                                acc[j], RANK, wmma::mem_row_major);
}

// ---------------------------------------------------------------------------
// Combine: g_xp[m][c] = f16(xp32[0][m][c] + xp32[1][m][c]); ext col 64 = 1.0
// ---------------------------------------------------------------------------
__global__ void combine_xp_kernel() {
    int i = blockIdx.x * blockDim.x + threadIdx.x;
    if (i >= M_ROWS * (RANK_EXT / 2)) return;
    int m  = i / (RANK_EXT / 2);
    int c2 = i % (RANK_EXT / 2);
    __half2 h;
    if (c2 < RANK / 2) {
        const float2* a = reinterpret_cast<const float2*>(g_xp32 + (size_t)m * RANK) + c2;
        const float2* b = reinterpret_cast<const float2*>(g_xp32 + (size_t)(M_ROWS + m) * RANK) + c2;
        float2 av = *a, bv = *b;
        h = __floats2half2_rn(av.x + bv.x, av.y + bv.y);
    } else if (c2 == RANK / 2) {
        h = __halves2half2(__float2half(1.0f), __float2half(0.0f));
    } else {
        h = __half2half2(__float2half(0.0f));
    }
    reinterpret_cast<__half2*>(g_xp)[(size_t)m * (RANK_EXT / 2) + c2] = h;
}

// ---------------------------------------------------------------------------
// GEMM2 (raw mma + permuted B): out[m,o] = (xp_ext . wout_ext)/64, K=80.
// CTA 64x128, 8 warps: wm=warp&3 (16 rows), wn=warp>>2 (64 cols).
// Ws rows permuted so each thread's 8 accumulators per 32-col group are 8
// CONSECUTIVE output columns -> register-direct STG.128 epilogue, 64B/row
// per instruction, no smem staging.
// ---------------------------------------------------------------------------
#define G2_LD 88  // half, padded

__global__ __launch_bounds__(256, 2)
void gemm2_kernel(float* __restrict__ out) {
    extern __shared__ __half sm2[];
    __half* Ps = sm2;               // [64][88]
    __half* Ws = sm2 + 64 * G2_LD;  // [128][88], rows permuted

    const int tid  = threadIdx.x;
    const int warp = tid >> 5;
    const int lane = tid & 31;
    const int wm   = warp & 3;   // 4 x 16 rows
    const int wn   = warp >> 2;  // 2 x 64 cols
    const int m0   = blockIdx.x * 64;
    const int n0   = blockIdx.y * 128;

    // --- loads: Ps 64x10 chunks (640) + Ws 128x10 chunks (1280, permuted) ---
    #pragma unroll
    for (int it = 0; it < 8; it++) {
        int c = tid + it * 256;
        if (c < 640) {
            int row = c / 10, off = c % 10;
            cp_async16(Ps + row * G2_LD + off * 8,
                       g_xp + (size_t)(m0 + row) * RANK_EXT + off * 8);
        } else if (c < 1920) {
            int cc = c - 640;
            int s = cc / 10, off = cc % 10;
            // permutation: smem row s -> gmem row n0 + wnn*64 + g*32 + q
            int wnn = s >> 6, rem = s & 63;
            int g = rem >> 5, w = rem & 31;
            int j = w >> 3, p = w & 7;
            int q = ((j >> 1) << 4) + ((p >> 1) << 2) + ((j & 1) << 1) + (p & 1);
            int gn = n0 + wnn * 64 + g * 32 + q;
            cp_async16(Ws + s * G2_LD + off * 8,
                       g_wout + (size_t)gn * RANK_EXT + off * 8);
        }
    }
    cp_async_commit();
    cp_async_wait<0>();
    __syncthreads();

    const unsigned ps_base = (unsigned)__cvta_generic_to_shared(Ps);
    const unsigned ws_base = (unsigned)__cvta_generic_to_shared(Ws);

    float acc[8][4];
    #pragma unroll
    for (int i = 0; i < 8; i++)
        #pragma unroll
        for (int e = 0; e < 4; e++) acc[i][e] = 0.0f;

    // ldmatrix lane->address components
    const int a_row = wm * 16 + (lane & 7) + ((lane >> 3) & 1) * 8;
    const int a_k   = (lane >> 4) * 8;
    const int b_row = wn * 64 + (lane & 7) + (lane >> 4) * 8;  // + g*32 + jp*16
    const int b_k   = ((lane >> 3) & 1) * 8;

    #pragma unroll
    for (int k4 = 0; k4 < 5; k4++) {   // K = 80
        unsigned a0, a1, a2, a3;
        {
            unsigned addr = ps_base + (unsigned)((a_row * G2_LD + k4 * 16 + a_k) * 2);
            asm volatile("ldmatrix.sync.aligned.m8n8.x4.shared.b16 {%0,%1,%2,%3}, [%4];"
                         : "=r"(a0), "=r"(a1), "=r"(a2), "=r"(a3) : "r"(addr));
        }
        #pragma unroll
        for (int g = 0; g < 2; g++) {
            #pragma unroll
            for (int jp = 0; jp < 2; jp++) {
                unsigned b0, b1, b2, b3;
                unsigned addr = ws_base +
                    (unsigned)(((b_row + g * 32 + jp * 16) * G2_LD + k4 * 16 + b_k) * 2);
                asm volatile("ldmatrix.sync.aligned.m8n8.x4.shared.b16 {%0,%1,%2,%3}, [%4];"
                             : "=r"(b0), "=r"(b1), "=r"(b2), "=r"(b3) : "r"(addr));
                float* c0 = acc[g * 4 + jp * 2];
                float* c1 = acc[g * 4 + jp * 2 + 1];
                asm volatile(
                    "mma.sync.aligned.m16n8k16.row.col.f32.f16.f16.f32 "
                    "{%0,%1,%2,%3}, {%4,%5,%6,%7}, {%8,%9}, {%0,%1,%2,%3};"
                    : "+f"(c0[0]), "+f"(c0[1]), "+f"(c0[2]), "+f"(c0[3])
                    : "r"(a0), "r"(a1), "r"(a2), "r"(a3), "r"(b0), "r"(b1));
                asm volatile(
                    "mma.sync.aligned.m16n8k16.row.col.f32.f16.f16.f32 "
                    "{%0,%1,%2,%3}, {%4,%5,%6,%7}, {%8,%9}, {%0,%1,%2,%3};"
                    : "+f"(c1[0]), "+f"(c1[1]), "+f"(c1[2]), "+f"(c1[3])
                    : "r"(a0), "r"(a1), "r"(a2), "r"(a3), "r"(b2), "r"(b3));
            }
        }
    }

    // --- register-direct coalesced epilogue ---
    const float s = 1.0f / (float)RANK;
    const int rlo = m0 + wm * 16 + (lane >> 2);
    const int cb  = (lane & 3) * 4;
    #pragma unroll
    for (int g = 0; g < 2; g++) {
        const int nb = n0 + wn * 64 + g * 32;
        float4 v;
        // row lo, cols nb+cb .. +3  (subtiles 0,1 of group)
        v.x = acc[g*4+0][0] * s; v.y = acc[g*4+0][1] * s;
        v.z = acc[g*4+1][0] * s; v.w = acc[g*4+1][1] * s;
        *reinterpret_cast<float4*>(&out[(size_t)rlo * OUT_F + nb + cb]) = v;
        // row lo, cols nb+16+cb (subtiles 2,3)
        v.x = acc[g*4+2][0] * s; v.y = acc[g*4+2][1] * s;
        v.z = acc[g*4+3][0] * s; v.w = acc[g*4+3][1] * s;
        *reinterpret_cast<float4*>(&out[(size_t)rlo * OUT_F + nb + 16 + cb]) = v;
        // row hi (+8)
        v.x = acc[g*4+0][2] * s; v.y = acc[g*4+0][3] * s;
        v.z = acc[g*4+1][2] * s; v.w = acc[g*4+1][3] * s;
        *reinterpret_cast<float4*>(&out[(size_t)(rlo + 8) * OUT_F + nb + cb]) = v;
        v.x = acc[g*4+2][2] * s; v.y = acc[g*4+2][3] * s;
        v.z = acc[g*4+3][2] * s; v.w = acc[g*4+3][3] * s;
        *reinterpret_cast<float4*>(&out[(size_t)(rlo + 8) * OUT_F + nb + 16 + cb]) = v;
    }
}

// ---------------------------------------------------------------------------
// Launcher
// ---------------------------------------------------------------------------
extern "C" void kernel_launch(void* const* d_in, const int* in_sizes, int n_in,
                              void* d_out, int out_size) {
    const float* x         = (const float*)d_in[0];
    const float* weight_in = (const float*)d_in[1];
    const float* weight_out= (const float*)d_in[2];
    const float* bias      = (const float*)d_in[3];
    const float* scale_in  = (const float*)d_in[4];
    const float* scale_out = (const float*)d_in[5];
    float* out = (float*)d_out;

    const int M = in_sizes[0] / IN_F;  // 8192

    {
        int total = RANK * IN_F / 4 + OUT_F * RANK / 4 + OUT_F;
        prep_weights_kernel<<<(total + 255) / 256, 256>>>(
            weight_in, weight_out, bias, scale_in, scale_out);
    }
    {
        size_t smem = 4 * (size_t)64 * G1_LDA * sizeof(__half);  // 36864
        dim3 grid(M / 64, 2);
        gemm1_kernel<<<grid, 256, smem>>>(x);
    }
    {
        int total = M_ROWS * (RANK_EXT / 2);
        combine_xp_kernel<<<(total + 255) / 256, 256>>>();
    }
    {
        size_t smem = (size_t)(64 + 128) * G2_LD * sizeof(__half);  // 33792
        dim3 grid(M / 64, OUT_F / 128);
        gemm2_kernel<<<grid, 256, smem>>>(out);
    }
}

// round 12
// speedup vs baseline: 1.1913x; 1.1320x over previous
#include <cuda_runtime.h>
#include <cuda_fp16.h>
#include <mma.h>

using namespace nvcuda;

#define IN_F   4096
#define OUT_F  4096
#define RANK   64
#define M_ROWS 8192

__device__ __half g_win [RANK * IN_F];        // [64][4096] f16
__device__ __half g_wout[OUT_F * RANK];       // [4096][64] f16
__device__ __half g_xp  [M_ROWS * RANK];      // [8192][64] f16
__device__ float  g_xp32[2 * M_ROWS * RANK];  // K-split partials, f32

// ---------------------------------------------------------------------------
// helpers
// ---------------------------------------------------------------------------
__device__ __forceinline__ void cp_async16(void* smem_dst, const void* gsrc) {
    unsigned s = (unsigned)__cvta_generic_to_shared(smem_dst);
    asm volatile("cp.async.cg.shared.global [%0], [%1], 16;\n" :: "r"(s), "l"(gsrc));
}
__device__ __forceinline__ void cp_async_commit() {
    asm volatile("cp.async.commit_group;\n");
}
template <int N>
__device__ __forceinline__ void cp_async_wait() {
    asm volatile("cp.async.wait_group %0;\n" :: "n"(N));
}

__device__ __forceinline__ void soft_threshold4(float4 w, float s,
                                                float& o0, float& o1, float& o2, float& o3) {
    float m0 = fabsf(w.x), m1 = fabsf(w.y), m2 = fabsf(w.z), m3 = fabsf(w.w);
    float lo01 = fminf(m0, m1), hi01 = fmaxf(m0, m1);
    float lo23 = fminf(m2, m3), hi23 = fmaxf(m2, m3);
    float t = fminf(fmaxf(lo01, lo23), fminf(hi01, hi23));  // 2nd-smallest
    o0 = copysignf(fmaxf(m0 - t, 0.0f), w.x) * s;
    o1 = copysignf(fmaxf(m1 - t, 0.0f), w.y) * s;
    o2 = copysignf(fmaxf(m2 - t, 0.0f), w.z) * s;
    o3 = copysignf(fmaxf(m3 - t, 0.0f), w.w) * s;
}

// ---------------------------------------------------------------------------
// Weight prep: threshold+scale -> g_win, g_wout
// ---------------------------------------------------------------------------
__global__ void prep_weights_kernel(const float* __restrict__ win,
                                    const float* __restrict__ wout,
                                    const float* __restrict__ scale_in,
                                    const float* __restrict__ scale_out) {
    const int NGI = RANK * IN_F / 4;    // 65536
    const int NGO = OUT_F * RANK / 4;   // 65536
    int idx = blockIdx.x * blockDim.x + threadIdx.x;
    if (idx < NGI) {
        float4 w = reinterpret_cast<const float4*>(win)[idx];
        float o0, o1, o2, o3;
        soft_threshold4(w, __ldg(scale_in), o0, o1, o2, o3);
        __half2* dst = reinterpret_cast<__half2*>(g_win) + idx * 2;
        dst[0] = __floats2half2_rn(o0, o1);
        dst[1] = __floats2half2_rn(o2, o3);
    } else if (idx < NGI + NGO) {
        int j = idx - NGI;
        float4 w = reinterpret_cast<const float4*>(wout)[j];
        float o0, o1, o2, o3;
        soft_threshold4(w, __ldg(scale_out), o0, o1, o2, o3);
        __half2* dst = reinterpret_cast<__half2*>(g_wout) + j * 2;
        dst[0] = __floats2half2_rn(o0, o1);
        dst[1] = __floats2half2_rn(o2, o3);
    }
}

// ---------------------------------------------------------------------------
// GEMM1 (K-split x2): xp32[ks][m,r] = sum_{k in half ks} f16(x[m,k])*g_win[r,k]
// BM=64, BK=64, grid (128, 2), 2 CTAs/SM, double-buffered, 2-deep prefetch.
// (unchanged from round 4 — best measured)
// ---------------------------------------------------------------------------
#define G1_LDA 72   // half, padded

__global__ __launch_bounds__(256, 2)
void gemm1_kernel(const float* __restrict__ x) {
    extern __shared__ __half sm1[];
    __half* A0 = sm1;                   // [64][72]
    __half* A1 = sm1 + 64 * G1_LDA;
    __half* B0 = sm1 + 2 * 64 * G1_LDA;
    __half* B1 = sm1 + 3 * 64 * G1_LDA;

    const int tid  = threadIdx.x;
    const int warp = tid >> 5;
    const int wm   = warp & 3;   // 16 rows
    const int wn   = warp >> 2;  // 32 cols
    const int m0   = blockIdx.x * 64;
    const int ks   = blockIdx.y;
    const int k0   = ks * (IN_F / 2);

    wmma::fragment<wmma::accumulator, 16, 16, 16, float> acc[2];
    wmma::fill_fragment(acc[0], 0.0f);
    wmma::fill_fragment(acc[1], 0.0f);

    const int NK = (IN_F / 2) / 64;  // 32

    float4 xa0[4], xa1[4];
    int4   wb0[2], wb1[2];

    auto ldx = [&](float4* xa, int kt) {
        #pragma unroll
        for (int it = 0; it < 4; it++) {
            int i = tid + it * 256;
            int row = i >> 4, c4 = i & 15;
            xa[it] = __ldcs(reinterpret_cast<const float4*>(
                &x[(size_t)(m0 + row) * IN_F + k0 + kt * 64 + c4 * 4]));
        }
    };
    auto ldw = [&](int4* wb, int kt) {
        #pragma unroll
        for (int it = 0; it < 2; it++) {
            int i = tid + it * 256;
            int row = i >> 3, c8 = i & 7;
            wb[it] = *reinterpret_cast<const int4*>(
                &g_win[row * IN_F + k0 + kt * 64 + c8 * 8]);
        }
    };
    auto stage = [&](__half* A, __half* B, const float4* xa, const int4* wb) {
        #pragma unroll
        for (int it = 0; it < 4; it++) {
            int i = tid + it * 256;
            int row = i >> 4, c4 = i & 15;
            __half* p = &A[row * G1_LDA + c4 * 4];
            reinterpret_cast<__half2*>(p)[0] = __floats2half2_rn(xa[it].x, xa[it].y);
            reinterpret_cast<__half2*>(p)[1] = __floats2half2_rn(xa[it].z, xa[it].w);
        }
        #pragma unroll
        for (int it = 0; it < 2; it++) {
            int i = tid + it * 256;
            int row = i >> 3, c8 = i & 7;
            *reinterpret_cast<int4*>(&B[row * G1_LDA + c8 * 8]) = wb[it];
        }
    };
    auto mma = [&](const __half* A, const __half* B) {
        #pragma unroll
        for (int k4 = 0; k4 < 4; k4++) {
            wmma::fragment<wmma::matrix_a, 16, 16, 16, __half, wmma::row_major> a;
            wmma::load_matrix_sync(a, &A[(wm * 16) * G1_LDA + k4 * 16], G1_LDA);
            #pragma unroll
            for (int j = 0; j < 2; j++) {
                wmma::fragment<wmma::matrix_b, 16, 16, 16, __half, wmma::col_major> b;
                wmma::load_matrix_sync(b, &B[(wn * 32 + j * 16) * G1_LDA + k4 * 16], G1_LDA);
                wmma::mma_sync(acc[j], a, b, acc[j]);
            }
        }
    };

    ldx(xa0, 0); ldw(wb0, 0);
    ldx(xa1, 1); ldw(wb1, 1);

    for (int kt = 0; kt < NK; kt += 2) {
        stage(A0, B0, xa0, wb0);
        __syncthreads();
        if (kt + 2 < NK) { ldx(xa0, kt + 2); ldw(wb0, kt + 2); }
        mma(A0, B0);

        stage(A1, B1, xa1, wb1);
        __syncthreads();
        if (kt + 3 < NK) { ldx(xa1, kt + 3); ldw(wb1, kt + 3); }
        mma(A1, B1);
    }

    float* outp = g_xp32 + (size_t)ks * M_ROWS * RANK;
    #pragma unroll
    for (int j = 0; j < 2; j++)
        wmma::store_matrix_sync(&outp[(size_t)(m0 + wm * 16) * RANK + wn * 32 + j * 16],
                                acc[j], RANK, wmma::mem_row_major);
}

// ---------------------------------------------------------------------------
// Combine: g_xp[m][c] = f16(xp32[0][m][c] + xp32[1][m][c])  ([8192][64])
// ---------------------------------------------------------------------------
__global__ void combine_xp_kernel() {
    int i = blockIdx.x * blockDim.x + threadIdx.x;   // over 8192*32 half2
    if (i >= M_ROWS * (RANK / 2)) return;
    const float2* a = reinterpret_cast<const float2*>(g_xp32) + i;
    const float2* b = reinterpret_cast<const float2*>(g_xp32 + (size_t)M_ROWS * RANK) + i;
    float2 av = *a, bv = *b;
    reinterpret_cast<__half2*>(g_xp)[i] = __floats2half2_rn(av.x + bv.x, av.y + bv.y);
}

// ---------------------------------------------------------------------------
// GEMM2: out[m,o] = (xp[m,:] . wout[o,:] + bias[o]) / 64   (K=64, no padding)
// BM=128, BN=128 (round-4 structure). Bias added via replicated-bias
// accumulator fragment; direct store_matrix_sync epilogue (measured best).
// ---------------------------------------------------------------------------
#define G2_LD  72    // half, padded (K=64)
#define G2_LDB 136   // bias_rep row stride (floats)

__global__ __launch_bounds__(256, 2)
void gemm2_kernel(const float* __restrict__ bias, float* __restrict__ out) {
    extern __shared__ __half sm2[];
    __half* Ps = sm2;                 // [128][72]  18432 B
    __half* Ws = sm2 + 128 * G2_LD;   // [128][72]  18432 B
    float* bias_rep = reinterpret_cast<float*>(sm2 + 2 * 128 * G2_LD);  // [16][136] 8704 B

    const int tid  = threadIdx.x;
    const int warp = tid >> 5;
    const int wm   = warp & 3;   // 32 rows
    const int wn   = warp >> 2;  // 64 cols
    const int m0   = blockIdx.x * 128;
    const int n0   = blockIdx.y * 128;

    // tile loads: 128 rows x 8 chunks each (stride 144B keeps 16B alignment)
    #pragma unroll
    for (int it = 0; it < 4; it++) {
        int c = tid + it * 256;
        int row = c >> 3, off = c & 7;
        cp_async16(Ps + row * G2_LD + off * 8,
                   g_xp + (size_t)(m0 + row) * RANK + off * 8);
    }
    #pragma unroll
    for (int it = 0; it < 4; it++) {
        int c = tid + it * 256;
        int row = c >> 3, off = c & 7;
        cp_async16(Ws + row * G2_LD + off * 8,
                   g_wout + (size_t)(n0 + row) * RANK + off * 8);
    }
    cp_async_commit();

    // bias_rep: 128 cols replicated over 16 rows
    if (tid < 128) {
        float bv = __ldg(&bias[n0 + tid]);
        #pragma unroll
        for (int r = 0; r < 16; r++) bias_rep[r * G2_LDB + tid] = bv;
    }

    cp_async_wait<0>();
    __syncthreads();

    wmma::fragment<wmma::accumulator, 16, 16, 16, float> acc[2][4];
    #pragma unroll
    for (int i = 0; i < 2; i++)
        #pragma unroll
        for (int j = 0; j < 4; j++) wmma::fill_fragment(acc[i][j], 0.0f);

    #pragma unroll
    for (int k4 = 0; k4 < 4; k4++) {   // K = 64
        wmma::fragment<wmma::matrix_a, 16, 16, 16, __half, wmma::row_major> a[2];
        #pragma unroll
        for (int i = 0; i < 2; i++)
            wmma::load_matrix_sync(a[i], &Ps[(wm * 32 + i * 16) * G2_LD + k4 * 16], G2_LD);
        #pragma unroll
        for (int j = 0; j < 4; j++) {
            wmma::fragment<wmma::matrix_b, 16, 16, 16, __half, wmma::col_major> b;
            wmma::load_matrix_sync(b, &Ws[(wn * 64 + j * 16) * G2_LD + k4 * 16], G2_LD);
            #pragma unroll
            for (int i = 0; i < 2; i++)
                wmma::mma_sync(acc[i][j], a[i], b, acc[i][j]);
        }
    }

    const float scaling = 1.0f / (float)RANK;
    #pragma unroll
    for (int i = 0; i < 2; i++)
        #pragma unroll
        for (int j = 0; j < 4; j++) {
            wmma::fragment<wmma::accumulator, 16, 16, 16, float> bf;
            wmma::load_matrix_sync(bf, &bias_rep[wn * 64 + j * 16], G2_LDB,
                                   wmma::mem_row_major);
            #pragma unroll
            for (int e = 0; e < acc[i][j].num_elements; e++)
                acc[i][j].x[e] = (acc[i][j].x[e] + bf.x[e]) * scaling;
            wmma::store_matrix_sync(
                &out[(size_t)(m0 + wm * 32 + i * 16) * OUT_F + n0 + wn * 64 + j * 16],
                acc[i][j], OUT_F, wmma::mem_row_major);
        }
}

// ---------------------------------------------------------------------------
// Launcher
// ---------------------------------------------------------------------------
extern "C" void kernel_launch(void* const* d_in, const int* in_sizes, int n_in,
                              void* d_out, int out_size) {
    const float* x         = (const float*)d_in[0];
    const float* weight_in = (const float*)d_in[1];
    const float* weight_out= (const float*)d_in[2];
    const float* bias      = (const float*)d_in[3];
    const float* scale_in  = (const float*)d_in[4];
    const float* scale_out = (const float*)d_in[5];
    float* out = (float*)d_out;

    const int M = in_sizes[0] / IN_F;  // 8192

    {
        int total = RANK * IN_F / 4 + OUT_F * RANK / 4;   // 131072
        prep_weights_kernel<<<(total + 255) / 256, 256>>>(
            weight_in, weight_out, scale_in, scale_out);
    }
    {
        size_t smem = 4 * (size_t)64 * G1_LDA * sizeof(__half);  // 36864
        dim3 grid(M / 64, 2);
        gemm1_kernel<<<grid, 256, smem>>>(x);
    }
    {
        int total = M_ROWS * (RANK / 2);
        combine_xp_kernel<<<(total + 255) / 256, 256>>>();
    }
    {
        size_t smem = 2 * (size_t)128 * G2_LD * sizeof(__half)   // 36864
                    + 16 * G2_LDB * sizeof(float);               // +8704 = 45568
        dim3 grid(M / 128, OUT_F / 128);
        gemm2_kernel<<<grid, 256, smem>>>(bias, out);
    }
}